// round 15
// baseline (speedup 1.0000x reference)
#include <cuda_runtime.h>
#include <cuda_fp16.h>
#include <math.h>

#define PI_F   3.14159265358979323846f
#define TWOPI_F 6.2831853071795864769f

typedef unsigned long long ull;

// ---------------- static device scratch ----------------
__device__ float   g_routed[256 * 128];
__device__ float   g_dw[8 * 4 * 128];
__device__ float   g_invnorm[128];
__device__ float2  g_spec0[128 * 1025];
__device__ float2  g_ldc2[128 * 1025];
__device__ float   g_frames[128 * 32 * 2048];
__device__ __half2 g_Fsig[16777216];         // 256 x 65536 (fp16)
__device__ __half2 g_Fres[4194304];          // 64 packed rows x 65536 (F_{2j} + i F_{2j+1}, unit-normed)
__device__ __half2 g_B[33554432];            // 512 x 65536 (inverse pass1, pre-scaled, fp16)
__device__ float   g_part[4 * 262144];

__device__ __forceinline__ float2 cmul(float2 a, float2 b) {
  return make_float2(a.x * b.x - a.y * b.y, a.x * b.y + a.y * b.x);
}
__device__ __forceinline__ unsigned rotl32(unsigned x, int r) {
  return (x << r) | (x >> (32 - r));
}
__device__ __forceinline__ ull f2u(float2 v) {
  ull r;
  asm("mov.b64 %0, {%1, %2};" : "=l"(r) : "f"(v.x), "f"(v.y));
  return r;
}
__device__ __forceinline__ float2 u2f(ull u) {
  float2 v;
  asm("mov.b64 {%0, %1}, %2;" : "=f"(v.x), "=f"(v.y) : "l"(u));
  return v;
}

// JAX threefry2x32, partitionable path: key=(0,123), counts=iota(u64), out0^out1.
__device__ __forceinline__ float noise_pm1(unsigned idx) {
  const unsigned ks0 = 0u, ks1 = 123u;
  const unsigned ks2 = ks0 ^ ks1 ^ 0x1BD11BDAu;
  unsigned x0 = ks0;
  unsigned x1 = idx + ks1;
#define TFR(r) { x0 += x1; x1 = rotl32(x1, r); x1 ^= x0; }
  TFR(13) TFR(15) TFR(26) TFR(6)
  x0 += ks1; x1 += ks2 + 1u;
  TFR(17) TFR(29) TFR(16) TFR(24)
  x0 += ks2; x1 += ks0 + 2u;
  TFR(13) TFR(15) TFR(26) TFR(6)
  x0 += ks0; x1 += ks1 + 3u;
  TFR(17) TFR(29) TFR(16) TFR(24)
  x0 += ks1; x1 += ks2 + 4u;
  TFR(13) TFR(15) TFR(26) TFR(6)
  x0 += ks2; x1 += ks0 + 5u;
#undef TFR
  unsigned bits = x0 ^ x1;
  float f = __uint_as_float((bits >> 9) | 0x3f800000u) - 1.0f;
  return f * 2.0f - 1.0f;
}

// ---------------- packed (f32x2) DFT-16, input bit-reversed, output natural ----------------
// SKIP1: inputs at odd q indices are exactly zero -> stage 1 is the identity
// (caller pre-duplicates r[odd]=r[even]); bit-identical to the full path.
#define PADD(d,a,b)   asm("add.rn.f32x2 %0,%1,%2;"    : "=l"(d) : "l"(a), "l"(b))
#define PSUB(d,a,b)   asm("fma.rn.f32x2 %0,%1,%2,%3;" : "=l"(d) : "l"(b), "l"(PN1), "l"(a))
#define PMUL(d,a,b)   asm("mul.rn.f32x2 %0,%1,%2;"    : "=l"(d) : "l"(a), "l"(b))
#define PFMA(d,a,b,c) asm("fma.rn.f32x2 %0,%1,%2,%3;" : "=l"(d) : "l"(a), "l"(b), "l"(c))
#define PROTP(d,b) asm("{.reg .f32 x,y,ny; mov.b64 {x,y},%1; neg.f32 ny,y; mov.b64 %0,{ny,x};}" : "=l"(d) : "l"(b))
#define PROTN(d,b) asm("{.reg .f32 x,y,nx; mov.b64 {x,y},%1; neg.f32 nx,x; mov.b64 %0,{y,nx};}" : "=l"(d) : "l"(b))

template <int S, bool SKIP1>
__device__ __forceinline__ void fft16p(ull* r) {
  ull PN1, PR2, PC1, PS1;
  asm("mov.b64 %0,{%1,%1};" : "=l"(PN1) : "f"(-1.0f));
  asm("mov.b64 %0,{%1,%1};" : "=l"(PR2) : "f"(0.7071067811865476f));
  asm("mov.b64 %0,{%1,%1};" : "=l"(PC1) : "f"(0.9238795325112867f));
  asm("mov.b64 %0,{%1,%1};" : "=l"(PS1) : "f"(0.3826834323650898f));
#define BF0(i0,i1) { ull s_, d_; PADD(s_, r[i0], r[i1]); PSUB(d_, r[i0], r[i1]); r[i0]=s_; r[i1]=d_; }
#define BFI(i0,i1) { ull t_, s_, d_; if (S > 0) { PROTP(t_, r[i1]); } else { PROTN(t_, r[i1]); } \
  PADD(s_, r[i0], t_); PSUB(d_, r[i0], t_); r[i0]=s_; r[i1]=d_; }
#define BFW(i0,i1, PWR, WRNEG, PWI, WINEG) { ull rt_, tm_, t_, s_, d_; \
  if (WINEG) { PROTN(rt_, r[i1]); } else { PROTP(rt_, r[i1]); } \
  PMUL(tm_, PWR, r[i1]); \
  PFMA(t_, PWI, rt_, tm_); \
  if (WRNEG) { PSUB(s_, r[i0], t_); PADD(d_, r[i0], t_); } \
  else       { PADD(s_, r[i0], t_); PSUB(d_, r[i0], t_); } \
  r[i0]=s_; r[i1]=d_; }
  if (!SKIP1) {
    BF0(0,1) BF0(2,3) BF0(4,5) BF0(6,7) BF0(8,9) BF0(10,11) BF0(12,13) BF0(14,15)
  }
  BF0(0,2) BFI(1,3) BF0(4,6) BFI(5,7) BF0(8,10) BFI(9,11) BF0(12,14) BFI(13,15)
  BF0(0,4)  BFW(1,5,  PR2, false, PR2, (S < 0)) BFI(2,6)   BFW(3,7,  PR2, true, PR2, (S > 0))
  BF0(8,12) BFW(9,13, PR2, false, PR2, (S < 0)) BFI(10,14) BFW(11,15,PR2, true, PR2, (S > 0))
  BF0(0,8)
  BFW(1,9,  PC1, false, PS1, (S < 0))
  BFW(2,10, PR2, false, PR2, (S < 0))
  BFW(3,11, PS1, false, PC1, (S < 0))
  BFI(4,12)
  BFW(5,13, PS1, true,  PC1, (S > 0))
  BFW(6,14, PR2, true,  PR2, (S > 0))
  BFW(7,15, PC1, true,  PS1, (S > 0))
#undef BF0
#undef BFI
#undef BFW
}

// ---------------- scalar DFT-8 (frames branch only) ----------------
template <int S>
__device__ __forceinline__ void fft8r(float2* r) {
  const float R2 = 0.7071067811865476f;
  const float sg = (float)S;
#define BF0(i0,i1) { float ax=r[i0].x, ay=r[i0].y, bx=r[i1].x, by=r[i1].y; \
  r[i0]=make_float2(ax+bx,ay+by); r[i1]=make_float2(ax-bx,ay-by); }
#define BFI(i0,i1) { float ax=r[i0].x, ay=r[i0].y, bx=r[i1].x, by=r[i1].y; \
  float tx=-sg*by, ty=sg*bx; \
  r[i0]=make_float2(ax+tx,ay+ty); r[i1]=make_float2(ax-tx,ay-ty); }
#define BFW(i0,i1,wr,wi) { float ax=r[i0].x, ay=r[i0].y, bx=r[i1].x, by=r[i1].y; \
  float tx=(wr)*bx-(wi)*by, ty=(wr)*by+(wi)*bx; \
  r[i0]=make_float2(ax+tx,ay+ty); r[i1]=make_float2(ax-tx,ay-ty); }
  BF0(0,1) BF0(2,3) BF0(4,5) BF0(6,7)
  BF0(0,2) BFI(1,3) BF0(4,6) BFI(5,7)
  BF0(0,4) BFW(1,5, R2, sg*R2) BFI(2,6) BFW(3,7, -R2, sg*R2)
#undef BF0
#undef BFI
#undef BFW
}

__device__ __forceinline__ void fill_T16(float2* T16, int tid) {
  if (tid < 256) {
    float sv, cv;
    __sincosf(-(TWOPI_F / 256.0f) * (float)((tid >> 4) * (tid & 15)), &sv, &cv);
    T16[tid] = make_float2(cv, sv);
  }
}

// FFT-256 on 16 threads x 16 regs (packed core). HALF: x[8..15] are exactly zero.
template <int S, bool BS, bool HALF = false>
__device__ __forceinline__ void fft256g(float2* x, int lane, float2* tileC,
                                        const float2* T16) {
  ull q[16];
  if (HALF) {
    q[0]=f2u(x[0]);  q[2]=f2u(x[4]);  q[4]=f2u(x[2]);  q[6]=f2u(x[6]);
    q[8]=f2u(x[1]);  q[10]=f2u(x[5]); q[12]=f2u(x[3]); q[14]=f2u(x[7]);
    q[1]=q[0]; q[3]=q[2]; q[5]=q[4]; q[7]=q[6];
    q[9]=q[8]; q[11]=q[10]; q[13]=q[12]; q[15]=q[14];
    fft16p<S, true>(q);
  } else {
    q[0]=f2u(x[0]);  q[1]=f2u(x[8]);  q[2]=f2u(x[4]);  q[3]=f2u(x[12]);
    q[4]=f2u(x[2]);  q[5]=f2u(x[10]); q[6]=f2u(x[6]);  q[7]=f2u(x[14]);
    q[8]=f2u(x[1]);  q[9]=f2u(x[9]);  q[10]=f2u(x[5]); q[11]=f2u(x[13]);
    q[12]=f2u(x[3]); q[13]=f2u(x[11]);q[14]=f2u(x[7]); q[15]=f2u(x[15]);
    fft16p<S, false>(q);
  }
  if (BS) __syncthreads(); else __syncwarp();
#pragma unroll
  for (int k1 = 0; k1 < 16; k1++) {
    float2 w = T16[k1 * 16 + lane];
    if (S > 0) w.y = -w.y;
    tileC[k1 * 17 + lane] = cmul(u2f(q[k1]), w);
  }
  if (BS) __syncthreads(); else __syncwarp();
  q[0]=f2u(tileC[lane*17+0]);  q[1]=f2u(tileC[lane*17+8]);
  q[2]=f2u(tileC[lane*17+4]);  q[3]=f2u(tileC[lane*17+12]);
  q[4]=f2u(tileC[lane*17+2]);  q[5]=f2u(tileC[lane*17+10]);
  q[6]=f2u(tileC[lane*17+6]);  q[7]=f2u(tileC[lane*17+14]);
  q[8]=f2u(tileC[lane*17+1]);  q[9]=f2u(tileC[lane*17+9]);
  q[10]=f2u(tileC[lane*17+5]); q[11]=f2u(tileC[lane*17+13]);
  q[12]=f2u(tileC[lane*17+3]); q[13]=f2u(tileC[lane*17+11]);
  q[14]=f2u(tileC[lane*17+7]); q[15]=f2u(tileC[lane*17+15]);
  fft16p<S, false>(q);
#pragma unroll
  for (int i = 0; i < 16; i++) x[i] = u2f(q[i]);
}

__device__ __forceinline__ void chain4(float2 w0, float2 s1, float2* c) {
  float2 s2 = cmul(s1, s1);
  float2 s4 = cmul(s2, s2);
  c[0] = w0;
  c[1] = cmul(w0, s4);
  c[2] = cmul(c[1], s4);
  c[3] = cmul(c[2], s4);
}

// ---------------- K1: merged prep (routed + dw + spec0) ----------------
__global__ void __launch_bounds__(256) k_prep(const float* __restrict__ cs,
                                              const float* __restrict__ defs,
                                              const float* __restrict__ router,
                                              const float* __restrict__ amp,
                                              const float* __restrict__ phase,
                                              const float* __restrict__ decay,
                                              float* __restrict__ out) {
  const int bx = blockIdx.x, tid = threadIdx.x;
  if (bx < 128) {
    int i = bx * 256 + tid;
    int f = i & 127, r = (i >> 7) & 31, bc = i >> 12;
    float acc = 0.0f;
#pragma unroll
    for (int c = 0; c < 16; c++)
      acc += cs[(bc * 16 + c) * 128 + f] * router[c * 32 + r];
    g_routed[i] = acc;
    out[262144 + i] = acc;
  } else if (bx < 132) {
    int i = (bx - 128) * 256 + tid;
    if (i >= 1024) return;
    int f = i & 127, bc = i >> 7;
    float v[4], mx = -1e30f;
#pragma unroll
    for (int e = 0; e < 4; e++) {
      float x = defs[(bc * 4 + e) * 128 + f] + (e == 0 ? 1.0f : 0.0f);
      v[e] = x; mx = fmaxf(mx, x);
    }
    float s = 0.0f;
#pragma unroll
    for (int e = 0; e < 4; e++) { v[e] = expf(v[e] - mx); s += v[e]; }
    float inv = 1.0f / s;
#pragma unroll
    for (int e = 0; e < 4; e++) g_dw[bc * 512 + e * 128 + f] = v[e] * inv;
  } else {
    int idx = bx - 132;
    int kb = idx % 5, re = idx / 5;
    int k = kb * 256 + tid;
    if (k >= 1025) return;
    int r = re >> 2, e = re & 3;
    int base = (r * 1025 + k) * 4 + e;
    float av = fabsf(amp[base]);
    float dc = 0.5f + 0.45f / (1.0f + expf(-decay[base]));
    float dcv = dc + 1e-12f;
    float ldc = logf(dcv);
    float ph = tanhf(phase[base]) * PI_F;
    float sv, cv; sincosf(ph, &sv, &cv);
    g_spec0[re * 1025 + k] = make_float2(av * dcv * cv, av * dcv * sv);
    g_ldc2[re * 1025 + k]  = make_float2(ldc, dcv);
  }
}

// ---------------- K2: merged frames2 + sig pass1 (independent work co-scheduled) ----------------
// Blocks [0,4096): sig pass1 (ALU/threefry heavy).
// Blocks [4096,5120): paired irfft(2048)*hann (smem/FMA heavy).
// Shared smem carve: [0,2048) T16; rest per branch.
__global__ void __launch_bounds__(256) k_fs() {
  __shared__ __align__(16) char smbuf[39168];
  float2* T16 = (float2*)smbuf;
  const int bx = blockIdx.x, tid = threadIdx.x;
  fill_T16(T16, tid);
  if (bx < 4096) {
    // ---- sig pass1 ----
    float2* tile = (float2*)(smbuf + 2048);
    float*  aux  = (float*)(smbuf + 36992);
    const int lane = tid >> 4, c = tid & 15;
    const int s = bx >> 4;
    const int b = (bx & 15) * 16 + c;
    if (tid < 128) aux[tid] = g_routed[s * 128 + tid];
    __syncthreads();   // T16 + aux ready
    float2 X[16];
#pragma unroll
    for (int n2 = 0; n2 < 8; n2++) {
      int n = b + 256 * (lane + 16 * n2);
      float pos = fminf(fmaxf((n + 0.5f) * (1.0f / 256.0f) - 0.5f, 0.0f), 127.0f);
      int lo = (int)pos;
      int hi = min(lo + 1, 127);
      float w = pos - (float)lo;
      X[n2] = make_float2(
          (aux[lo] * (1.0f - w) + aux[hi] * w) * noise_pm1((unsigned)(s * 32768 + n)),
          0.0f);
    }
    fft256g<-1, true, true>(X, lane, tile + c * 273, T16);
    float sv, cv;
    __sincosf(-(TWOPI_F / 65536.0f) * (float)(lane * b), &sv, &cv);
    float2 w0 = make_float2(cv, sv);
    __sincosf(-(TWOPI_F / 65536.0f) * (float)(16 * b), &sv, &cv);
    float2 s1 = make_float2(cv, sv);
    float2 cc[4];
    chain4(w0, s1, cc);
    __half2* dst = g_Fsig + (size_t)s * 65536 + b;
#pragma unroll
    for (int t = 0; t < 4; t++) {
#pragma unroll
      for (int j = 0; j < 4; j++) {
        int k2 = 4 * j + t;
        float2 z = cmul(X[k2], cc[j]);
        dst[(lane + 16 * k2) * 256] = __floats2half2_rn(z.x, z.y);
        cc[j] = cmul(cc[j], s1);
      }
    }
  } else {
    // ---- paired irfft(2048)*hann ----
    float2* SM = (float2*)(smbuf + 2048);
    const int idx = bx - 4096;
    const int sub = tid >> 7, lt = tid & 127;
    const int g = lt >> 4, gl = lt & 15;
    const int re = idx >> 3;
    const int p = (idx & 7) * 2 + sub;
    const int f0 = 2 * p;
    const float2* sp0 = g_spec0 + re * 1025;
    const float2* sl  = g_ldc2  + re * 1025;
    float2 X[16];
#pragma unroll
    for (int n2 = 0; n2 < 16; n2++) {
      int n = 8 * (gl + 16 * n2) + g;
      int mir = n > 1024;
      int k = mir ? 2048 - n : n;
      float2 c0 = sp0[k];
      float2 ld = sl[k];
      float e0 = __expf((float)f0 * ld.x);
      float sx = c0.x * e0;
      float sy = (mir ? -c0.y : c0.y) * e0;
      if (n == 0 || n == 1024) sy = 0.0f;
      X[n2] = make_float2(sx - sy * ld.y, sy + sx * ld.y);
    }
    __syncthreads();   // T16 ready
    fft256g<1, false>(X, gl, SM + (sub * 8 + g) * 273, T16);
    __syncthreads();
    {
      float sv, cv;
      __sincosf((TWOPI_F / 2048.0f) * (float)(g * gl), &sv, &cv);
      float2 w0 = make_float2(cv, sv);
      __sincosf((TWOPI_F / 2048.0f) * (float)(g * 16), &sv, &cv);
      float2 s1 = make_float2(cv, sv);
      float2 cc[4];
      chain4(w0, s1, cc);
      float2* tp = SM + sub * 2320;
#pragma unroll
      for (int t = 0; t < 4; t++) {
#pragma unroll
        for (int j = 0; j < 4; j++) {
          int k2 = 4 * j + t;
          int k1 = gl + 16 * k2;
          tp[k1 * 9 + g] = cmul(X[k2], cc[j]);
          cc[j] = cmul(cc[j], s1);
        }
      }
    }
    __syncthreads();
    const float2* tp = SM + sub * 2320;
    float* fa = g_frames + ((size_t)re * 32 + f0) * 2048;
    float* fb = fa + 2048;
#pragma unroll
    for (int h = 0; h < 2; h++) {
      int k1 = lt + 128 * h;
      float2 q[8];
      q[0] = tp[k1 * 9 + 0]; q[1] = tp[k1 * 9 + 4];
      q[2] = tp[k1 * 9 + 2]; q[3] = tp[k1 * 9 + 6];
      q[4] = tp[k1 * 9 + 1]; q[5] = tp[k1 * 9 + 5];
      q[6] = tp[k1 * 9 + 3]; q[7] = tp[k1 * 9 + 7];
      fft8r<1>(q);
#pragma unroll
      for (int k2 = 0; k2 < 8; k2++) {
        int t = k1 + 256 * k2;
        float sc = (0.5f - 0.5f * __cosf((TWOPI_F / 2048.0f) * (float)t)) * (1.0f / 2048.0f);
        fa[t] = q[k2].x * sc;
        fb[t] = q[k2].y * sc;
      }
    }
  }
}

// ---------------- K3: invnorm (overlap-add sum of squares) ----------------
__global__ void __launch_bounds__(1024) k_oa() {
  const int re = blockIdx.x, tid = threadIdx.x;
  const float* F = g_frames + (size_t)re * 65536;
  float ss = 0.0f;
#pragma unroll
  for (int f = 0; f < 32; f++) {
    float v = F[f * 2048 + tid];
    if (f > 0) v += F[(f - 1) * 2048 + 1024 + tid];
    ss += v * v;
  }
#pragma unroll
  for (int o = 16; o > 0; o >>= 1) ss += __shfl_xor_sync(0xffffffffu, ss, o);
  __shared__ float red[32];
  if ((tid & 31) == 0) red[tid >> 5] = ss;
  __syncthreads();
  if (tid < 32) {
    float v = red[tid];
#pragma unroll
    for (int o = 16; o > 0; o >>= 1) v += __shfl_xor_sync(0xffffffffu, v, o);
    if (tid == 0) g_invnorm[re] = 1.0f / (sqrtf(v) + 1e-8f);
  }
}

// ---------------- K4: packed-res pass1 (w = res0*inv0 + i*res1*inv1) ----------------
__global__ void __launch_bounds__(256) k_resmid() {
  __shared__ float2 tile[16 * 273];
  __shared__ float2 T16[256];
  const int bx = blockIdx.x, tid = threadIdx.x;
  fill_T16(T16, tid);
  const int lane = tid >> 4, c = tid & 15;
  const int rj = bx >> 4;              // 0..63
  const int b = (bx & 15) * 16 + c;
  const float* F0 = g_frames + (size_t)(2 * rj) * 65536;
  const float* F1 = F0 + 65536;
  const float inv0 = g_invnorm[2 * rj];
  const float inv1 = g_invnorm[2 * rj + 1];
  float2 X[16];
#pragma unroll
  for (int n2 = 0; n2 < 8; n2++) {
    int n = b + 256 * (lane + 16 * n2);
    int f = n >> 10, t = n & 1023;
    float v0 = F0[f * 2048 + t];
    float v1 = F1[f * 2048 + t];
    if (f > 0) {
      v0 += F0[(f - 1) * 2048 + 1024 + t];
      v1 += F1[(f - 1) * 2048 + 1024 + t];
    }
    X[n2] = make_float2(v0 * inv0, v1 * inv1);
  }
  __syncthreads();                     // T16 ready
  fft256g<-1, true, true>(X, lane, tile + c * 273, T16);
  float sv, cv;
  __sincosf(-(TWOPI_F / 65536.0f) * (float)(lane * b), &sv, &cv);
  float2 w0 = make_float2(cv, sv);
  __sincosf(-(TWOPI_F / 65536.0f) * (float)(16 * b), &sv, &cv);
  float2 s1 = make_float2(cv, sv);
  float2 cc[4];
  chain4(w0, s1, cc);
  __half2* dst = g_Fres + (size_t)rj * 65536 + b;
#pragma unroll
  for (int t = 0; t < 4; t++) {
#pragma unroll
    for (int j = 0; j < 4; j++) {
      int k2 = 4 * j + t;
      float2 z = cmul(X[k2], cc[j]);
      dst[(lane + 16 * k2) * 256] = __floats2half2_rn(z.x, z.y);
      cc[j] = cmul(cc[j], s1);
    }
  }
}

// ---------------- K5: fused packed-res pass2 (smem-resident) + fwd pass2(sig, prefetched)
//                  + product + inverse pass1 ----------------
#define FUSED3_SMEM 107776
__global__ void __launch_bounds__(256) k_fused3() {
  extern __shared__ char dsm[];
  float2*  tile = (float2*)dsm;
  float2*  T16  = (float2*)(dsm + 34944);
  __half2* SR   = (__half2*)(dsm + 36992);
  __half2* H2a  = (__half2*)(dsm + 72832);
  __half2* H2b  = (__half2*)(dsm + 90304);
  const int tid = threadIdx.x;
  fill_T16(T16, tid);
  const int c = tid >> 4, lane = tid & 15;
  const int r = blockIdx.y;
  const int d = blockIdx.x * 16 + c;
  __syncthreads();
  __half2* SRg = SR + c * 560;
#pragma unroll
  for (int rp = 0; rp < 2; rp++) {
    const __half2* row = g_Fres + (size_t)(2 * r + rp) * 65536 + d * 256;
    float2 X[16];
#pragma unroll
    for (int n2 = 0; n2 < 16; n2++) X[n2] = __half22float2(row[lane + 16 * n2]);
    fft256g<-1, false>(X, lane, tile + c * 273, T16);
#pragma unroll
    for (int k2 = 0; k2 < 16; k2++)
      SRg[rp * 273 + lane + 16 * k2] = __floats2half2_rn(X[k2].x, X[k2].y);
  }
  __syncwarp();
  float sv, cv;
  __sincosf((TWOPI_F / 65536.0f) * (float)(lane * d), &sv, &cv);
  const float scl = 1.0f / 65536.0f;
  const float2 w0 = make_float2(cv * scl, sv * scl);
  __sincosf((TWOPI_F / 65536.0f) * (float)(16 * d), &sv, &cv);
  const float2 s1 = make_float2(cv, sv);
  __half2 P[16];
  {
    const __half2* srow = g_Fsig + (size_t)r * 65536 + d * 256;
#pragma unroll
    for (int n2 = 0; n2 < 16; n2++) P[n2] = srow[lane + 16 * n2];
  }
  int pp = 0;
  for (int bc = 0; bc < 8; bc++) {
    const int s = bc * 32 + r;
    float2 X[16];
#pragma unroll
    for (int n2 = 0; n2 < 16; n2++) X[n2] = __half22float2(P[n2]);
    if (bc < 7) {
      const __half2* srow = g_Fsig + (size_t)(s + 32) * 65536 + d * 256;
#pragma unroll
      for (int n2 = 0; n2 < 16; n2++) P[n2] = srow[lane + 16 * n2];
    }
    fft256g<-1, false>(X, lane, tile + c * 273, T16);
#pragma unroll
    for (int hb = 0; hb < 2; hb++) {
      float2 Y[16];
#pragma unroll
      for (int k = 0; k < 16; k++) {
        Y[k] = cmul(X[k], __half22float2(SRg[hb * 273 + lane + 16 * k]));
      }
      fft256g<1, false>(Y, lane, tile + c * 273, T16);
      float2 cc[4];
      chain4(w0, s1, cc);
      __half2* H2 = pp ? H2b : H2a;
      __half2* st = H2 + c * 273;
      __syncwarp();
#pragma unroll
      for (int t = 0; t < 4; t++) {
#pragma unroll
        for (int j = 0; j < 4; j++) {
          int k2 = 4 * j + t;
          float2 z = cmul(Y[k2], cc[j]);
          st[lane + 16 * k2] = __floats2half2_rn(z.x, z.y);
          cc[j] = cmul(cc[j], s1);
        }
      }
      __syncthreads();
      const int oc = tid & 15, jb = tid >> 4;
      __half2* dst = g_B + ((size_t)(s * 2 + hb)) * 65536 + blockIdx.x * 16 + oc;
      const __half2* sr2 = H2 + oc * 273;
#pragma unroll
      for (int m = 0; m < 16; m++)
        dst[(jb + 16 * m) * 256] = sr2[jb + 16 * m];
      pp ^= 1;
    }
  }
}

// ---------------- K6: fused inverse pass2 + deformation mix + tanh ----------------
__global__ void __launch_bounds__(256) k_invfinal(const float* __restrict__ gains) {
  __shared__ float2 tile[16 * 273];
  __shared__ float2 T16[256];
  __shared__ float dw[512];
  __shared__ float ga[32];
  const int tid = threadIdx.x;
  fill_T16(T16, tid);
  const int c = tid >> 4, lane = tid & 15;
  const int bc = blockIdx.y, rz = blockIdx.z;
  const int bp = blockIdx.x * 16 + c;
  for (int i = tid; i < 512; i += 256) dw[i] = g_dw[bc * 512 + i];
  if (tid < 32) ga[tid] = fabsf(gains[tid]);
  __syncthreads();
  float d0[8], d1[8], d2[8], d3[8], accv[8];
#pragma unroll
  for (int k2 = 0; k2 < 8; k2++) {
    int n = bp + 256 * (lane + 16 * k2);
    float pos = fminf(fmaxf((n + 0.5f) * (1.0f / 256.0f) - 0.5f, 0.0f), 127.0f);
    int lo = (int)pos;
    int hi = min(lo + 1, 127);
    float w = pos - (float)lo;
    d0[k2] = dw[lo]       * (1.0f - w) + dw[hi]       * w;
    d1[k2] = dw[128 + lo] * (1.0f - w) + dw[128 + hi] * w;
    d2[k2] = dw[256 + lo] * (1.0f - w) + dw[256 + hi] * w;
    d3[k2] = dw[384 + lo] * (1.0f - w) + dw[384 + hi] * w;
    accv[k2] = 0.0f;
  }
  for (int rr = 0; rr < 8; rr++) {
    const int r = rz * 8 + rr;
    const size_t base = ((size_t)((bc * 32 + r) * 2)) * 65536 + (size_t)bp * 256;
    float2 Y0[8];
    {
      const __half2* row = g_B + base;
      float2 X[16];
#pragma unroll
      for (int n2 = 0; n2 < 16; n2++) X[n2] = __half22float2(row[lane + 16 * n2]);
      fft256g<1, false>(X, lane, tile + c * 273, T16);
#pragma unroll
      for (int k2 = 0; k2 < 8; k2++) Y0[k2] = X[k2];
    }
    float2 X[16];
    {
      const __half2* row = g_B + base + 65536;
#pragma unroll
      for (int n2 = 0; n2 < 16; n2++) X[n2] = __half22float2(row[lane + 16 * n2]);
      fft256g<1, false>(X, lane, tile + c * 273, T16);
    }
    const float gn = ga[r];
#pragma unroll
    for (int k2 = 0; k2 < 8; k2++) {
      float sx = d0[k2] * Y0[k2].x + d1[k2] * Y0[k2].y + d2[k2] * X[k2].x + d3[k2] * X[k2].y;
      sx = fminf(fmaxf(sx * gn, -15.0f), 15.0f);
      float z = __expf(2.0f * sx);
      accv[k2] += __fdividef(z - 1.0f, z + 1.0f);
    }
  }
  float* dst = g_part + (size_t)rz * 262144 + bc * 32768;
#pragma unroll
  for (int k2 = 0; k2 < 8; k2++) {
    int n = bp + 256 * (lane + 16 * k2);
    dst[n] = accv[k2];
  }
}

// ---------------- K7: reduce 4 partials ----------------
__global__ void __launch_bounds__(256) k_reduce(float* __restrict__ out) {
  int i = blockIdx.x * 256 + threadIdx.x;
  out[i] = g_part[i] + g_part[262144 + i] + g_part[524288 + i] + g_part[786432 + i];
}

extern "C" void kernel_launch(void* const* d_in, const int* in_sizes, int n_in,
                              void* d_out, int out_size) {
  const float* cs     = (const float*)d_in[0];
  const float* defs   = (const float*)d_in[1];
  const float* router = (const float*)d_in[2];
  const float* amp    = (const float*)d_in[3];
  const float* phase  = (const float*)d_in[4];
  const float* decay  = (const float*)d_in[5];
  const float* gains  = (const float*)d_in[6];
  float* out = (float*)d_out;

  static int smem_set = 0;
  if (!smem_set) {
    cudaFuncSetAttribute(k_fused3, cudaFuncAttributeMaxDynamicSharedMemorySize,
                         FUSED3_SMEM);
    smem_set = 1;
  }

  k_prep<<<772, 256>>>(cs, defs, router, amp, phase, decay, out);
  k_fs<<<5120, 256>>>();               // frames2 + sig pass1 co-scheduled
  k_oa<<<128, 1024>>>();
  k_resmid<<<1024, 256>>>();
  k_fused3<<<dim3(16, 32), 256, FUSED3_SMEM>>>();
  k_invfinal<<<dim3(16, 8, 4), 256>>>(gains);
  k_reduce<<<1024, 256>>>(out);
}

// round 16
// speedup vs baseline: 1.0175x; 1.0175x over previous
#include <cuda_runtime.h>
#include <cuda_fp16.h>
#include <math.h>

#define PI_F   3.14159265358979323846f
#define TWOPI_F 6.2831853071795864769f

typedef unsigned long long ull;

// ---------------- static device scratch ----------------
__device__ float   g_routed[256 * 128];
__device__ float   g_dw[8 * 4 * 128];
__device__ float   g_invnorm[128];
__device__ float2  g_spec0[128 * 1025];
__device__ float2  g_ldc2[128 * 1025];
__device__ float   g_frames[128 * 32 * 2048];
__device__ __half2 g_Fsig[16777216];         // 256 x 65536 (fp16)
__device__ __half2 g_Fres[4194304];          // 64 packed rows x 65536 (F_{2j} + i F_{2j+1}, unit-normed)
__device__ __half2 g_B[33554432];            // 512 x 65536 (inverse pass1, pre-scaled, fp16)
__device__ float   g_part[4 * 262144];

__device__ __forceinline__ float2 cmul(float2 a, float2 b) {
  return make_float2(a.x * b.x - a.y * b.y, a.x * b.y + a.y * b.x);
}
__device__ __forceinline__ unsigned rotl32(unsigned x, int r) {
  return (x << r) | (x >> (32 - r));
}
__device__ __forceinline__ ull f2u(float2 v) {
  ull r;
  asm("mov.b64 %0, {%1, %2};" : "=l"(r) : "f"(v.x), "f"(v.y));
  return r;
}
__device__ __forceinline__ float2 u2f(ull u) {
  float2 v;
  asm("mov.b64 {%0, %1}, %2;" : "=f"(v.x), "=f"(v.y) : "l"(u));
  return v;
}

// JAX threefry2x32, partitionable path: key=(0,123), counts=iota(u64), out0^out1.
__device__ __forceinline__ float noise_pm1(unsigned idx) {
  const unsigned ks0 = 0u, ks1 = 123u;
  const unsigned ks2 = ks0 ^ ks1 ^ 0x1BD11BDAu;
  unsigned x0 = ks0;
  unsigned x1 = idx + ks1;
#define TFR(r) { x0 += x1; x1 = rotl32(x1, r); x1 ^= x0; }
  TFR(13) TFR(15) TFR(26) TFR(6)
  x0 += ks1; x1 += ks2 + 1u;
  TFR(17) TFR(29) TFR(16) TFR(24)
  x0 += ks2; x1 += ks0 + 2u;
  TFR(13) TFR(15) TFR(26) TFR(6)
  x0 += ks0; x1 += ks1 + 3u;
  TFR(17) TFR(29) TFR(16) TFR(24)
  x0 += ks1; x1 += ks2 + 4u;
  TFR(13) TFR(15) TFR(26) TFR(6)
  x0 += ks2; x1 += ks0 + 5u;
#undef TFR
  unsigned bits = x0 ^ x1;
  float f = __uint_as_float((bits >> 9) | 0x3f800000u) - 1.0f;
  return f * 2.0f - 1.0f;
}

// ---------------- packed (f32x2) DFT-16, input bit-reversed, output natural ----------------
// SKIP1: odd q slots duplicate even ones (zero-padded input) -> stage 1 is identity.
// OUTH : only outputs 0..7 needed -> last stage computes only the '+' arm.
#define PADD(d,a,b)   asm("add.rn.f32x2 %0,%1,%2;"    : "=l"(d) : "l"(a), "l"(b))
#define PSUB(d,a,b)   asm("fma.rn.f32x2 %0,%1,%2,%3;" : "=l"(d) : "l"(b), "l"(PN1), "l"(a))
#define PMUL(d,a,b)   asm("mul.rn.f32x2 %0,%1,%2;"    : "=l"(d) : "l"(a), "l"(b))
#define PFMA(d,a,b,c) asm("fma.rn.f32x2 %0,%1,%2,%3;" : "=l"(d) : "l"(a), "l"(b), "l"(c))
#define PROTP(d,b) asm("{.reg .f32 x,y,ny; mov.b64 {x,y},%1; neg.f32 ny,y; mov.b64 %0,{ny,x};}" : "=l"(d) : "l"(b))
#define PROTN(d,b) asm("{.reg .f32 x,y,nx; mov.b64 {x,y},%1; neg.f32 nx,x; mov.b64 %0,{y,nx};}" : "=l"(d) : "l"(b))

template <int S, bool SKIP1, bool OUTH>
__device__ __forceinline__ void fft16p(ull* r) {
  ull PN1, PR2, PC1, PS1;
  asm("mov.b64 %0,{%1,%1};" : "=l"(PN1) : "f"(-1.0f));
  asm("mov.b64 %0,{%1,%1};" : "=l"(PR2) : "f"(0.7071067811865476f));
  asm("mov.b64 %0,{%1,%1};" : "=l"(PC1) : "f"(0.9238795325112867f));
  asm("mov.b64 %0,{%1,%1};" : "=l"(PS1) : "f"(0.3826834323650898f));
#define BF0(i0,i1) { ull s_, d_; PADD(s_, r[i0], r[i1]); PSUB(d_, r[i0], r[i1]); r[i0]=s_; r[i1]=d_; }
#define BFI(i0,i1) { ull t_, s_, d_; if (S > 0) { PROTP(t_, r[i1]); } else { PROTN(t_, r[i1]); } \
  PADD(s_, r[i0], t_); PSUB(d_, r[i0], t_); r[i0]=s_; r[i1]=d_; }
#define BFW(i0,i1, PWR, WRNEG, PWI, WINEG) { ull rt_, tm_, t_, s_, d_; \
  if (WINEG) { PROTN(rt_, r[i1]); } else { PROTP(rt_, r[i1]); } \
  PMUL(tm_, PWR, r[i1]); \
  PFMA(t_, PWI, rt_, tm_); \
  if (WRNEG) { PSUB(s_, r[i0], t_); PADD(d_, r[i0], t_); } \
  else       { PADD(s_, r[i0], t_); PSUB(d_, r[i0], t_); } \
  r[i0]=s_; r[i1]=d_; }
#define BF0H(i0,i1) { ull s_; PADD(s_, r[i0], r[i1]); r[i0]=s_; }
#define BFIH(i0,i1) { ull t_, s_; if (S > 0) { PROTP(t_, r[i1]); } else { PROTN(t_, r[i1]); } \
  PADD(s_, r[i0], t_); r[i0]=s_; }
#define BFWH(i0,i1, PWR, WRNEG, PWI, WINEG) { ull rt_, tm_, t_, s_; \
  if (WINEG) { PROTN(rt_, r[i1]); } else { PROTP(rt_, r[i1]); } \
  PMUL(tm_, PWR, r[i1]); \
  PFMA(t_, PWI, rt_, tm_); \
  if (WRNEG) { PSUB(s_, r[i0], t_); } else { PADD(s_, r[i0], t_); } \
  r[i0]=s_; }
  if (!SKIP1) {
    BF0(0,1) BF0(2,3) BF0(4,5) BF0(6,7) BF0(8,9) BF0(10,11) BF0(12,13) BF0(14,15)
  }
  BF0(0,2) BFI(1,3) BF0(4,6) BFI(5,7) BF0(8,10) BFI(9,11) BF0(12,14) BFI(13,15)
  BF0(0,4)  BFW(1,5,  PR2, false, PR2, (S < 0)) BFI(2,6)   BFW(3,7,  PR2, true, PR2, (S > 0))
  BF0(8,12) BFW(9,13, PR2, false, PR2, (S < 0)) BFI(10,14) BFW(11,15,PR2, true, PR2, (S > 0))
  if (!OUTH) {
    BF0(0,8)
    BFW(1,9,  PC1, false, PS1, (S < 0))
    BFW(2,10, PR2, false, PR2, (S < 0))
    BFW(3,11, PS1, false, PC1, (S < 0))
    BFI(4,12)
    BFW(5,13, PS1, true,  PC1, (S > 0))
    BFW(6,14, PR2, true,  PR2, (S > 0))
    BFW(7,15, PC1, true,  PS1, (S > 0))
  } else {
    BF0H(0,8)
    BFWH(1,9,  PC1, false, PS1, (S < 0))
    BFWH(2,10, PR2, false, PR2, (S < 0))
    BFWH(3,11, PS1, false, PC1, (S < 0))
    BFIH(4,12)
    BFWH(5,13, PS1, true,  PC1, (S > 0))
    BFWH(6,14, PR2, true,  PR2, (S > 0))
    BFWH(7,15, PC1, true,  PS1, (S > 0))
  }
#undef BF0
#undef BFI
#undef BFW
#undef BF0H
#undef BFIH
#undef BFWH
}

// ---------------- scalar DFT-8 (k_frames2 only) ----------------
template <int S>
__device__ __forceinline__ void fft8r(float2* r) {
  const float R2 = 0.7071067811865476f;
  const float sg = (float)S;
#define BF0(i0,i1) { float ax=r[i0].x, ay=r[i0].y, bx=r[i1].x, by=r[i1].y; \
  r[i0]=make_float2(ax+bx,ay+by); r[i1]=make_float2(ax-bx,ay-by); }
#define BFI(i0,i1) { float ax=r[i0].x, ay=r[i0].y, bx=r[i1].x, by=r[i1].y; \
  float tx=-sg*by, ty=sg*bx; \
  r[i0]=make_float2(ax+tx,ay+ty); r[i1]=make_float2(ax-tx,ay-ty); }
#define BFW(i0,i1,wr,wi) { float ax=r[i0].x, ay=r[i0].y, bx=r[i1].x, by=r[i1].y; \
  float tx=(wr)*bx-(wi)*by, ty=(wr)*by+(wi)*bx; \
  r[i0]=make_float2(ax+tx,ay+ty); r[i1]=make_float2(ax-tx,ay-ty); }
  BF0(0,1) BF0(2,3) BF0(4,5) BF0(6,7)
  BF0(0,2) BFI(1,3) BF0(4,6) BFI(5,7)
  BF0(0,4) BFW(1,5, R2, sg*R2) BFI(2,6) BFW(3,7, -R2, sg*R2)
#undef BF0
#undef BFI
#undef BFW
}

__device__ __forceinline__ void fill_T16(float2* T16, int tid) {
  if (tid < 256) {
    float sv, cv;
    __sincosf(-(TWOPI_F / 256.0f) * (float)((tid >> 4) * (tid & 15)), &sv, &cv);
    T16[tid] = make_float2(cv, sv);
  }
}

// FFT-256 on 16 threads x 16 regs (packed core).
// HALF: x[8..15] exactly zero (only x[0..7] read). OUTH: only x[0..7] written.
template <int S, bool BS, bool HALF = false, bool OUTH = false>
__device__ __forceinline__ void fft256g(float2* x, int lane, float2* tileC,
                                        const float2* T16) {
  ull q[16];
  if (HALF) {
    q[0]=f2u(x[0]);  q[2]=f2u(x[4]);  q[4]=f2u(x[2]);  q[6]=f2u(x[6]);
    q[8]=f2u(x[1]);  q[10]=f2u(x[5]); q[12]=f2u(x[3]); q[14]=f2u(x[7]);
    q[1]=q[0]; q[3]=q[2]; q[5]=q[4]; q[7]=q[6];
    q[9]=q[8]; q[11]=q[10]; q[13]=q[12]; q[15]=q[14];
    fft16p<S, true, false>(q);
  } else {
    q[0]=f2u(x[0]);  q[1]=f2u(x[8]);  q[2]=f2u(x[4]);  q[3]=f2u(x[12]);
    q[4]=f2u(x[2]);  q[5]=f2u(x[10]); q[6]=f2u(x[6]);  q[7]=f2u(x[14]);
    q[8]=f2u(x[1]);  q[9]=f2u(x[9]);  q[10]=f2u(x[5]); q[11]=f2u(x[13]);
    q[12]=f2u(x[3]); q[13]=f2u(x[11]);q[14]=f2u(x[7]); q[15]=f2u(x[15]);
    fft16p<S, false, false>(q);
  }
  if (BS) __syncthreads(); else __syncwarp();
#pragma unroll
  for (int k1 = 0; k1 < 16; k1++) {
    float2 w = T16[k1 * 16 + lane];
    if (S > 0) w.y = -w.y;
    tileC[k1 * 17 + lane] = cmul(u2f(q[k1]), w);
  }
  if (BS) __syncthreads(); else __syncwarp();
  q[0]=f2u(tileC[lane*17+0]);  q[1]=f2u(tileC[lane*17+8]);
  q[2]=f2u(tileC[lane*17+4]);  q[3]=f2u(tileC[lane*17+12]);
  q[4]=f2u(tileC[lane*17+2]);  q[5]=f2u(tileC[lane*17+10]);
  q[6]=f2u(tileC[lane*17+6]);  q[7]=f2u(tileC[lane*17+14]);
  q[8]=f2u(tileC[lane*17+1]);  q[9]=f2u(tileC[lane*17+9]);
  q[10]=f2u(tileC[lane*17+5]); q[11]=f2u(tileC[lane*17+13]);
  q[12]=f2u(tileC[lane*17+3]); q[13]=f2u(tileC[lane*17+11]);
  q[14]=f2u(tileC[lane*17+7]); q[15]=f2u(tileC[lane*17+15]);
  fft16p<S, false, OUTH>(q);
  if (OUTH) {
#pragma unroll
    for (int i = 0; i < 8; i++) x[i] = u2f(q[i]);
  } else {
#pragma unroll
    for (int i = 0; i < 16; i++) x[i] = u2f(q[i]);
  }
}

__device__ __forceinline__ void chain4(float2 w0, float2 s1, float2* c) {
  float2 s2 = cmul(s1, s1);
  float2 s4 = cmul(s2, s2);
  c[0] = w0;
  c[1] = cmul(w0, s4);
  c[2] = cmul(c[1], s4);
  c[3] = cmul(c[2], s4);
}

// ---------------- K1: merged prep (routed + dw + spec0) ----------------
__global__ void __launch_bounds__(256) k_prep(const float* __restrict__ cs,
                                              const float* __restrict__ defs,
                                              const float* __restrict__ router,
                                              const float* __restrict__ amp,
                                              const float* __restrict__ phase,
                                              const float* __restrict__ decay,
                                              float* __restrict__ out) {
  const int bx = blockIdx.x, tid = threadIdx.x;
  if (bx < 128) {
    int i = bx * 256 + tid;
    int f = i & 127, r = (i >> 7) & 31, bc = i >> 12;
    float acc = 0.0f;
#pragma unroll
    for (int c = 0; c < 16; c++)
      acc += cs[(bc * 16 + c) * 128 + f] * router[c * 32 + r];
    g_routed[i] = acc;
    out[262144 + i] = acc;
  } else if (bx < 132) {
    int i = (bx - 128) * 256 + tid;
    if (i >= 1024) return;
    int f = i & 127, bc = i >> 7;
    float v[4], mx = -1e30f;
#pragma unroll
    for (int e = 0; e < 4; e++) {
      float x = defs[(bc * 4 + e) * 128 + f] + (e == 0 ? 1.0f : 0.0f);
      v[e] = x; mx = fmaxf(mx, x);
    }
    float s = 0.0f;
#pragma unroll
    for (int e = 0; e < 4; e++) { v[e] = expf(v[e] - mx); s += v[e]; }
    float inv = 1.0f / s;
#pragma unroll
    for (int e = 0; e < 4; e++) g_dw[bc * 512 + e * 128 + f] = v[e] * inv;
  } else {
    int idx = bx - 132;
    int kb = idx % 5, re = idx / 5;
    int k = kb * 256 + tid;
    if (k >= 1025) return;
    int r = re >> 2, e = re & 3;
    int base = (r * 1025 + k) * 4 + e;
    float av = fabsf(amp[base]);
    float dc = 0.5f + 0.45f / (1.0f + expf(-decay[base]));
    float dcv = dc + 1e-12f;
    float ldc = logf(dcv);
    float ph = tanhf(phase[base]) * PI_F;
    float sv, cv; sincosf(ph, &sv, &cv);
    g_spec0[re * 1025 + k] = make_float2(av * dcv * cv, av * dcv * sv);
    g_ldc2[re * 1025 + k]  = make_float2(ldc, dcv);
  }
}

// ---------------- K2: paired irfft(2048)*hann ----------------
__global__ void __launch_bounds__(256) k_frames2() {
  __shared__ float2 SM[4640];
  __shared__ float2 T16[256];
  const int tid = threadIdx.x;
  fill_T16(T16, tid);
  const int sub = tid >> 7, lt = tid & 127;
  const int g = lt >> 4, gl = lt & 15;
  const int re = blockIdx.y;
  const int p = blockIdx.x * 2 + sub;
  const int f0 = 2 * p;
  const float2* sp0 = g_spec0 + re * 1025;
  const float2* sl  = g_ldc2  + re * 1025;
  float2 X[16];
#pragma unroll
  for (int n2 = 0; n2 < 16; n2++) {
    int n = 8 * (gl + 16 * n2) + g;
    int mir = n > 1024;
    int k = mir ? 2048 - n : n;
    float2 c0 = sp0[k];
    float2 ld = sl[k];
    float e0 = __expf((float)f0 * ld.x);
    float sx = c0.x * e0;
    float sy = (mir ? -c0.y : c0.y) * e0;
    if (n == 0 || n == 1024) sy = 0.0f;
    X[n2] = make_float2(sx - sy * ld.y, sy + sx * ld.y);
  }
  __syncthreads();
  fft256g<1, false>(X, gl, SM + (sub * 8 + g) * 273, T16);
  __syncthreads();
  {
    float sv, cv;
    __sincosf((TWOPI_F / 2048.0f) * (float)(g * gl), &sv, &cv);
    float2 w0 = make_float2(cv, sv);
    __sincosf((TWOPI_F / 2048.0f) * (float)(g * 16), &sv, &cv);
    float2 s1 = make_float2(cv, sv);
    float2 cc[4];
    chain4(w0, s1, cc);
    float2* tp = SM + sub * 2320;
#pragma unroll
    for (int t = 0; t < 4; t++) {
#pragma unroll
      for (int j = 0; j < 4; j++) {
        int k2 = 4 * j + t;
        int k1 = gl + 16 * k2;
        tp[k1 * 9 + g] = cmul(X[k2], cc[j]);
        cc[j] = cmul(cc[j], s1);
      }
    }
  }
  __syncthreads();
  const float2* tp = SM + sub * 2320;
  float* fa = g_frames + ((size_t)re * 32 + f0) * 2048;
  float* fb = fa + 2048;
#pragma unroll
  for (int h = 0; h < 2; h++) {
    int k1 = lt + 128 * h;
    float2 q[8];
    q[0] = tp[k1 * 9 + 0]; q[1] = tp[k1 * 9 + 4];
    q[2] = tp[k1 * 9 + 2]; q[3] = tp[k1 * 9 + 6];
    q[4] = tp[k1 * 9 + 1]; q[5] = tp[k1 * 9 + 5];
    q[6] = tp[k1 * 9 + 3]; q[7] = tp[k1 * 9 + 7];
    fft8r<1>(q);
#pragma unroll
    for (int k2 = 0; k2 < 8; k2++) {
      int t = k1 + 256 * k2;
      float sc = (0.5f - 0.5f * __cosf((TWOPI_F / 2048.0f) * (float)t)) * (1.0f / 2048.0f);
      fa[t] = q[k2].x * sc;
      fb[t] = q[k2].y * sc;
    }
  }
}

// ---------------- K3: invnorm (overlap-add sum of squares) ----------------
__global__ void __launch_bounds__(1024) k_oa() {
  const int re = blockIdx.x, tid = threadIdx.x;
  const float* F = g_frames + (size_t)re * 65536;
  float ss = 0.0f;
#pragma unroll
  for (int f = 0; f < 32; f++) {
    float v = F[f * 2048 + tid];
    if (f > 0) v += F[(f - 1) * 2048 + 1024 + tid];
    ss += v * v;
  }
#pragma unroll
  for (int o = 16; o > 0; o >>= 1) ss += __shfl_xor_sync(0xffffffffu, ss, o);
  __shared__ float red[32];
  if ((tid & 31) == 0) red[tid >> 5] = ss;
  __syncthreads();
  if (tid < 32) {
    float v = red[tid];
#pragma unroll
    for (int o = 16; o > 0; o >>= 1) v += __shfl_xor_sync(0xffffffffu, v, o);
    if (tid == 0) g_invnorm[re] = 1.0f / (sqrtf(v) + 1e-8f);
  }
}

// ---------------- K4: merged mid (sig pass1 || packed-res pass1), HALF FFTs ----------------
__global__ void __launch_bounds__(256) k_mid() {
  __shared__ float2 tile[16 * 273];
  __shared__ float2 T16[256];
  __shared__ float  aux[128];
  const int bx = blockIdx.x, tid = threadIdx.x;
  fill_T16(T16, tid);
  const int lane = tid >> 4, c = tid & 15;
  float2 X[16];
  int b;
  __half2* dst;
  if (bx < 4096) {                     // ---- sig pass1 ----
    const int s = bx >> 4;
    b = (bx & 15) * 16 + c;
    if (tid < 128) aux[tid] = g_routed[s * 128 + tid];
    __syncthreads();
#pragma unroll
    for (int n2 = 0; n2 < 8; n2++) {
      int n = b + 256 * (lane + 16 * n2);
      float pos = fminf(fmaxf((n + 0.5f) * (1.0f / 256.0f) - 0.5f, 0.0f), 127.0f);
      int lo = (int)pos;
      int hi = min(lo + 1, 127);
      float w = pos - (float)lo;
      X[n2] = make_float2(
          (aux[lo] * (1.0f - w) + aux[hi] * w) * noise_pm1((unsigned)(s * 32768 + n)),
          0.0f);
    }
    dst = g_Fsig + (size_t)s * 65536 + b;
  } else {                             // ---- packed res pass1: w = res0*inv0 + i*res1*inv1 ----
    const int t0 = bx - 4096;
    const int rj = t0 >> 4;            // 0..63
    b = (t0 & 15) * 16 + c;
    const float* F0 = g_frames + (size_t)(2 * rj) * 65536;
    const float* F1 = F0 + 65536;
    const float inv0 = g_invnorm[2 * rj];
    const float inv1 = g_invnorm[2 * rj + 1];
#pragma unroll
    for (int n2 = 0; n2 < 8; n2++) {
      int n = b + 256 * (lane + 16 * n2);
      int f = n >> 10, t = n & 1023;
      float v0 = F0[f * 2048 + t];
      float v1 = F1[f * 2048 + t];
      if (f > 0) {
        v0 += F0[(f - 1) * 2048 + 1024 + t];
        v1 += F1[(f - 1) * 2048 + 1024 + t];
      }
      X[n2] = make_float2(v0 * inv0, v1 * inv1);
    }
    dst = g_Fres + (size_t)rj * 65536 + b;
    __syncthreads();                   // T16 ready
  }
  fft256g<-1, true, true>(X, lane, tile + c * 273, T16);
  float sv, cv;
  __sincosf(-(TWOPI_F / 65536.0f) * (float)(lane * b), &sv, &cv);
  float2 w0 = make_float2(cv, sv);
  __sincosf(-(TWOPI_F / 65536.0f) * (float)(16 * b), &sv, &cv);
  float2 s1 = make_float2(cv, sv);
  float2 cc[4];
  chain4(w0, s1, cc);
#pragma unroll
  for (int t = 0; t < 4; t++) {
#pragma unroll
    for (int j = 0; j < 4; j++) {
      int k2 = 4 * j + t;
      float2 z = cmul(X[k2], cc[j]);
      dst[(lane + 16 * k2) * 256] = __floats2half2_rn(z.x, z.y);
      cc[j] = cmul(cc[j], s1);
    }
  }
}

// ---------------- K5: fused packed-res pass2 (smem-resident) + fwd pass2(sig, prefetched)
//                  + product + inverse pass1 (ping-pong staging) ----------------
#define FUSED3_SMEM 107776
__global__ void __launch_bounds__(256) k_fused3() {
  extern __shared__ char dsm[];
  float2*  tile = (float2*)dsm;
  float2*  T16  = (float2*)(dsm + 34944);
  __half2* SR   = (__half2*)(dsm + 36992);
  __half2* H2a  = (__half2*)(dsm + 72832);
  __half2* H2b  = (__half2*)(dsm + 90304);
  const int tid = threadIdx.x;
  fill_T16(T16, tid);
  const int c = tid >> 4, lane = tid & 15;
  const int r = blockIdx.y;
  const int d = blockIdx.x * 16 + c;
  __syncthreads();
  __half2* SRg = SR + c * 560;
#pragma unroll
  for (int rp = 0; rp < 2; rp++) {
    const __half2* row = g_Fres + (size_t)(2 * r + rp) * 65536 + d * 256;
    float2 X[16];
#pragma unroll
    for (int n2 = 0; n2 < 16; n2++) X[n2] = __half22float2(row[lane + 16 * n2]);
    fft256g<-1, false>(X, lane, tile + c * 273, T16);
#pragma unroll
    for (int k2 = 0; k2 < 16; k2++)
      SRg[rp * 273 + lane + 16 * k2] = __floats2half2_rn(X[k2].x, X[k2].y);
  }
  __syncwarp();
  float sv, cv;
  __sincosf((TWOPI_F / 65536.0f) * (float)(lane * d), &sv, &cv);
  const float scl = 1.0f / 65536.0f;
  const float2 w0 = make_float2(cv * scl, sv * scl);
  __sincosf((TWOPI_F / 65536.0f) * (float)(16 * d), &sv, &cv);
  const float2 s1 = make_float2(cv, sv);
  __half2 P[16];
  {
    const __half2* srow = g_Fsig + (size_t)r * 65536 + d * 256;
#pragma unroll
    for (int n2 = 0; n2 < 16; n2++) P[n2] = srow[lane + 16 * n2];
  }
  int pp = 0;
  for (int bc = 0; bc < 8; bc++) {
    const int s = bc * 32 + r;
    float2 X[16];
#pragma unroll
    for (int n2 = 0; n2 < 16; n2++) X[n2] = __half22float2(P[n2]);
    if (bc < 7) {
      const __half2* srow = g_Fsig + (size_t)(s + 32) * 65536 + d * 256;
#pragma unroll
      for (int n2 = 0; n2 < 16; n2++) P[n2] = srow[lane + 16 * n2];
    }
    fft256g<-1, false>(X, lane, tile + c * 273, T16);
#pragma unroll
    for (int hb = 0; hb < 2; hb++) {
      float2 Y[16];
#pragma unroll
      for (int k = 0; k < 16; k++) {
        Y[k] = cmul(X[k], __half22float2(SRg[hb * 273 + lane + 16 * k]));
      }
      fft256g<1, false>(Y, lane, tile + c * 273, T16);
      float2 cc[4];
      chain4(w0, s1, cc);
      __half2* H2 = pp ? H2b : H2a;
      __half2* st = H2 + c * 273;
      __syncwarp();
#pragma unroll
      for (int t = 0; t < 4; t++) {
#pragma unroll
        for (int j = 0; j < 4; j++) {
          int k2 = 4 * j + t;
          float2 z = cmul(Y[k2], cc[j]);
          st[lane + 16 * k2] = __floats2half2_rn(z.x, z.y);
          cc[j] = cmul(cc[j], s1);
        }
      }
      __syncthreads();
      const int oc = tid & 15, jb = tid >> 4;
      __half2* dst = g_B + ((size_t)(s * 2 + hb)) * 65536 + blockIdx.x * 16 + oc;
      const __half2* sr2 = H2 + oc * 273;
#pragma unroll
      for (int m = 0; m < 16; m++)
        dst[(jb + 16 * m) * 256] = sr2[jb + 16 * m];
      pp ^= 1;
    }
  }
}

// ---------------- K6: fused inverse pass2 (OUTH) + deformation mix + tanh ----------------
__global__ void __launch_bounds__(256) k_invfinal(const float* __restrict__ gains) {
  __shared__ float2 tile[16 * 273];
  __shared__ float2 T16[256];
  __shared__ float dw[512];
  __shared__ float ga[32];
  const int tid = threadIdx.x;
  fill_T16(T16, tid);
  const int c = tid >> 4, lane = tid & 15;
  const int bc = blockIdx.y, rz = blockIdx.z;
  const int bp = blockIdx.x * 16 + c;
  for (int i = tid; i < 512; i += 256) dw[i] = g_dw[bc * 512 + i];
  if (tid < 32) ga[tid] = fabsf(gains[tid]);
  __syncthreads();
  float d0[8], d1[8], d2[8], d3[8], accv[8];
#pragma unroll
  for (int k2 = 0; k2 < 8; k2++) {
    int n = bp + 256 * (lane + 16 * k2);
    float pos = fminf(fmaxf((n + 0.5f) * (1.0f / 256.0f) - 0.5f, 0.0f), 127.0f);
    int lo = (int)pos;
    int hi = min(lo + 1, 127);
    float w = pos - (float)lo;
    d0[k2] = dw[lo]       * (1.0f - w) + dw[hi]       * w;
    d1[k2] = dw[128 + lo] * (1.0f - w) + dw[128 + hi] * w;
    d2[k2] = dw[256 + lo] * (1.0f - w) + dw[256 + hi] * w;
    d3[k2] = dw[384 + lo] * (1.0f - w) + dw[384 + hi] * w;
    accv[k2] = 0.0f;
  }
  for (int rr = 0; rr < 8; rr++) {
    const int r = rz * 8 + rr;
    const size_t base = ((size_t)((bc * 32 + r) * 2)) * 65536 + (size_t)bp * 256;
    float2 Y0[8];
    {
      const __half2* row = g_B + base;
      float2 X[16];
#pragma unroll
      for (int n2 = 0; n2 < 16; n2++) X[n2] = __half22float2(row[lane + 16 * n2]);
      fft256g<1, false, false, true>(X, lane, tile + c * 273, T16);
#pragma unroll
      for (int k2 = 0; k2 < 8; k2++) Y0[k2] = X[k2];
    }
    float2 X[16];
    {
      const __half2* row = g_B + base + 65536;
#pragma unroll
      for (int n2 = 0; n2 < 16; n2++) X[n2] = __half22float2(row[lane + 16 * n2]);
      fft256g<1, false, false, true>(X, lane, tile + c * 273, T16);
    }
    const float gn = ga[r];
#pragma unroll
    for (int k2 = 0; k2 < 8; k2++) {
      float sx = d0[k2] * Y0[k2].x + d1[k2] * Y0[k2].y + d2[k2] * X[k2].x + d3[k2] * X[k2].y;
      sx = fminf(fmaxf(sx * gn, -15.0f), 15.0f);
      float z = __expf(2.0f * sx);
      accv[k2] += __fdividef(z - 1.0f, z + 1.0f);
    }
  }
  float* dst = g_part + (size_t)rz * 262144 + bc * 32768;
#pragma unroll
  for (int k2 = 0; k2 < 8; k2++) {
    int n = bp + 256 * (lane + 16 * k2);
    dst[n] = accv[k2];
  }
}

// ---------------- K7: reduce 4 partials ----------------
__global__ void __launch_bounds__(256) k_reduce(float* __restrict__ out) {
  int i = blockIdx.x * 256 + threadIdx.x;
  out[i] = g_part[i] + g_part[262144 + i] + g_part[524288 + i] + g_part[786432 + i];
}

extern "C" void kernel_launch(void* const* d_in, const int* in_sizes, int n_in,
                              void* d_out, int out_size) {
  const float* cs     = (const float*)d_in[0];
  const float* defs   = (const float*)d_in[1];
  const float* router = (const float*)d_in[2];
  const float* amp    = (const float*)d_in[3];
  const float* phase  = (const float*)d_in[4];
  const float* decay  = (const float*)d_in[5];
  const float* gains  = (const float*)d_in[6];
  float* out = (float*)d_out;

  static int smem_set = 0;
  if (!smem_set) {
    cudaFuncSetAttribute(k_fused3, cudaFuncAttributeMaxDynamicSharedMemorySize,
                         FUSED3_SMEM);
    smem_set = 1;
  }

  k_prep<<<772, 256>>>(cs, defs, router, amp, phase, decay, out);
  k_frames2<<<dim3(8, 128), 256>>>();
  k_oa<<<128, 1024>>>();
  k_mid<<<5120, 256>>>();
  k_fused3<<<dim3(16, 32), 256, FUSED3_SMEM>>>();
  k_invfinal<<<dim3(16, 8, 4), 256>>>(gains);
  k_reduce<<<1024, 256>>>(out);
}